// round 4
// baseline (speedup 1.0000x reference)
#include <cuda_runtime.h>
#include <cuda_bf16.h>

#define BS   8
#define CH   256
#define TLEN 512
#define PBIN 16
#define SRAT 4

// 4 MB transposed-input scratch: (b, t, c) layout so channel gathers coalesce.
__device__ float g_tr[BS * TLEN * CH];

// ---------------------------------------------------------------------------
// Kernel 1: transpose (b, ch, t) -> (b, t, ch), tiled 32x32 through smem.
// ---------------------------------------------------------------------------
__global__ void transpose_kernel(const float* __restrict__ in) {
    __shared__ float tile[32][33];
    const int b  = blockIdx.z;
    const int t0 = blockIdx.x * 32;
    const int c0 = blockIdx.y * 32;
    const int tx = threadIdx.x;          // 0..31
    const int ty = threadIdx.y;          // 0..7

    const float* inb  = in   + (size_t)b * CH * TLEN;
    float*       outb = g_tr + (size_t)b * TLEN * CH;

    #pragma unroll
    for (int j = 0; j < 32; j += 8)
        tile[ty + j][tx] = inb[(size_t)(c0 + ty + j) * TLEN + (t0 + tx)];
    __syncthreads();
    #pragma unroll
    for (int j = 0; j < 32; j += 8)
        outb[(size_t)(t0 + ty + j) * CH + (c0 + tx)] = tile[tx][ty + j];
}

// ---------------------------------------------------------------------------
// Kernel 2: 256-thread block = 4 ROIs (64 threads each, thread owns 4 chans).
//   Per-ROI subgroup synced with its own named barrier. Two 8-bin passes keep
//   staging smem at 36KB/block; __launch_bounds__(256,6) caps regs at 42 so
//   6 blocks/SM (48 warps) fit -> occupancy is the lever, L1 is the pipe.
// ---------------------------------------------------------------------------
__global__ __launch_bounds__(256, 6) void roialign_kernel(const float* __restrict__ rois,
                                                          float4* __restrict__ out) {
    const int sub = threadIdx.x >> 6;        // which ROI in this block (0..3)
    const int l   = threadIdx.x & 63;        // lane within ROI subgroup
    const int n   = blockIdx.x * 4 + sub;    // ROI index

    __shared__ uint4  s_desc [4][PBIN * SRAT];   // 64 sample descriptors / ROI
    __shared__ float4 s_stage[4][8][64];         // 8-bin staging / ROI (rotated)

    const int bar_id = sub + 1;

    // ---- Phase A: per-sample descriptors (thread i == sample i) ----
    {
        const float bf    = __ldg(&rois[n * 3 + 0]);
        const float start = __ldg(&rois[n * 3 + 1]);
        const float end   = __ldg(&rois[n * 3 + 2]);
        const float roi_len = fmaxf(end - start, 1.0f);
        const float bin     = roi_len * (1.0f / (float)PBIN);

        const int p = l >> 2;                // bin
        const int s = l & 3;                 // sample
        const float x = start + ((float)p + ((float)s + 0.5f) * 0.25f) * bin;
        const bool valid = (x >= -1.0f) && (x <= (float)TLEN);
        const float xc = fminf(fmaxf(x, 0.0f), (float)(TLEN - 1));
        const int xl = (int)floorf(xc);
        const int xh = min(xl + 1, TLEN - 1);
        const float lx = xc - (float)xl;
        const int b = (int)bf;

        uint4 d;
        d.x = (unsigned)(((b << 9) + xl) << 10);   // byte offset of row xl
        d.y = (unsigned)(((b << 9) + xh) << 10);   // byte offset of row xh
        d.z = __float_as_uint(valid ? (1.0f - lx) : 0.0f);
        d.w = __float_as_uint(valid ? lx : 0.0f);
        s_desc[sub][l] = d;
    }
    asm volatile("bar.sync %0, %1;" :: "r"(bar_id), "r"(64) : "memory");

    const char* base = (const char*)g_tr + l * 16;     // this thread's channels
    float4* outn = out + (size_t)n * (CH * PBIN / 4);
    const float* st = (const float*)s_stage[sub];

    #pragma unroll
    for (int h = 0; h < 2; h++) {
        // ---- Phase B: gather + accumulate 8 bins, stage with rotation r ----
        #pragma unroll 1
        for (int r = 0; r < 8; r++) {
            const int p = 8 * h + r;
            float4 acc = make_float4(0.0f, 0.0f, 0.0f, 0.0f);
            #pragma unroll
            for (int s = 0; s < SRAT; s++) {
                const uint4 d = s_desc[sub][p * SRAT + s];
                const float4 vlo = *(const float4*)(base + d.x);
                const float4 vhi = *(const float4*)(base + d.y);
                const float wlo = __uint_as_float(d.z);
                const float whi = __uint_as_float(d.w);
                acc.x += vlo.x * wlo + vhi.x * whi;
                acc.y += vlo.y * wlo + vhi.y * whi;
                acc.z += vlo.z * wlo + vhi.z * whi;
                acc.w += vlo.w * wlo + vhi.w * whi;
            }
            acc.x *= 0.25f; acc.y *= 0.25f; acc.z *= 0.25f; acc.w *= 0.25f;
            s_stage[sub][r][(l + r) & 63] = acc;       // conflict-free STS.128
        }
        asm volatile("bar.sync %0, %1;" :: "r"(bar_id), "r"(64) : "memory");

        // ---- Phase C: coalesced writeback of this half ----
        #pragma unroll
        for (int k = 0; k < 8; k++) {
            const int m  = l + 64 * k;
            const int c  = m >> 1;           // channel
            const int g2 = m & 1;            // which float4 within the half
            float4 v;
            #pragma unroll
            for (int j = 0; j < 4; j++) {
                const int r = 4 * g2 + j;    // staged bin row
                ((float*)&v)[j] = st[r * 256 + (((c >> 2) + r) & 63) * 4 + (c & 3)];
            }
            outn[c * 4 + 2 * h + g2] = v;
        }
        asm volatile("bar.sync %0, %1;" :: "r"(bar_id), "r"(64) : "memory");
    }
}

extern "C" void kernel_launch(void* const* d_in, const int* in_sizes, int n_in,
                              void* d_out, int out_size) {
    const float* input = (const float*)d_in[0];
    const float* rois  = (const float*)d_in[1];
    float4*      out   = (float4*)d_out;

    const int N = in_sizes[1] / 3;       // 2048 ROIs

    dim3 tgrid(TLEN / 32, CH / 32, BS);  // (16, 8, 8)
    dim3 tblk(32, 8);
    transpose_kernel<<<tgrid, tblk>>>(input);

    roialign_kernel<<<N / 4, 256>>>(rois, out);
}

// round 5
// speedup vs baseline: 1.0755x; 1.0755x over previous
#include <cuda_runtime.h>
#include <cuda_bf16.h>

#define BS   8
#define CH   256
#define TLEN 512
#define PBIN 16
#define SRAT 4

// Transposed-input scratch: (b, t, c) layout so channel gathers coalesce.
// +16 zero-initialized pad rows: contiguous-mode may load (weight=0) rows
// slightly past t=511 of the last batch; pad is never written, stays 0.
__device__ float g_tr[(BS * TLEN + 16) * CH];

// ---------------------------------------------------------------------------
// Kernel 1: transpose (b, ch, t) -> (b, t, ch), tiled 32x32 through smem.
// ---------------------------------------------------------------------------
__global__ void transpose_kernel(const float* __restrict__ in) {
    __shared__ float tile[32][33];
    const int b  = blockIdx.z;
    const int t0 = blockIdx.x * 32;
    const int c0 = blockIdx.y * 32;
    const int tx = threadIdx.x;          // 0..31
    const int ty = threadIdx.y;          // 0..7

    const float* inb  = in   + (size_t)b * CH * TLEN;
    float*       outb = g_tr + (size_t)b * TLEN * CH;

    #pragma unroll
    for (int j = 0; j < 32; j += 8)
        tile[ty + j][tx] = inb[(size_t)(c0 + ty + j) * TLEN + (t0 + tx)];
    __syncthreads();
    #pragma unroll
    for (int j = 0; j < 32; j += 8)
        outb[(size_t)(t0 + ty + j) * CH + (c0 + tx)] = tile[tx][ty + j];
}

// ---------------------------------------------------------------------------
// Kernel 2: one 64-thread block per ROI; thread owns 4 consecutive channels.
//   Two uniform per-ROI modes:
//   - CONTIG (bin_size <= 8, ~60% of ROIs): per-bin row-weight vectors; hot
//     loop reads a short contiguous row range (2..9 rows) instead of 8
//     per-sample row loads -> fewer gather bytes + denser L1 lines.
//   - SAMPLE (long ROIs): R2's proven per-sample descriptor path, unroll 2.
//   Staging + coalesced writeback identical to the R2 champion.
// ---------------------------------------------------------------------------
__global__ __launch_bounds__(64) void roialign_kernel(const float* __restrict__ rois,
                                                      float4* __restrict__ out) {
    const int n = blockIdx.x;
    const int l = threadIdx.x;           // 0..63

    __shared__ uint4    s_desc[PBIN * SRAT];    // SAMPLE mode descriptors
    __shared__ float    s_w[PBIN][10];          // CONTIG mode row weights
    __shared__ unsigned s_off[PBIN];            // CONTIG: byte offset of row r0
    __shared__ int      s_cnt[PBIN];            // CONTIG: rows touched per bin
    __shared__ float4   s_stage[PBIN * 64];     // [p][rotated float4-col]

    const float bf    = __ldg(&rois[n * 3 + 0]);
    const float start = __ldg(&rois[n * 3 + 1]);
    const float end   = __ldg(&rois[n * 3 + 2]);
    const float roi_len = fmaxf(end - start, 1.0f);
    const float bin     = roi_len * (1.0f / (float)PBIN);
    const int   b       = (int)bf;
    const bool  contig  = (bin <= 8.0f);        // uniform per block

    // ---- Phase A: descriptors ----
    if (contig) {
        if (l < PBIN) {
            const int p = l;
            #pragma unroll
            for (int j = 0; j < 10; j++) s_w[p][j] = 0.0f;

            const float x0  = start + ((float)p + 0.125f) * bin;
            const float xc0 = fminf(fmaxf(x0, 0.0f), (float)(TLEN - 1));
            const int   r0  = (int)floorf(xc0);
            int maxidx = 0;
            #pragma unroll
            for (int s = 0; s < SRAT; s++) {
                const float x = start + ((float)p + ((float)s + 0.5f) * 0.25f) * bin;
                const bool valid = (x >= -1.0f) && (x <= (float)TLEN);
                const float xc = fminf(fmaxf(x, 0.0f), (float)(TLEN - 1));
                const int xl = (int)floorf(xc);
                const int xh = min(xl + 1, TLEN - 1);
                const float lx = xc - (float)xl;
                s_w[p][xl - r0] += valid ? (1.0f - lx) * 0.25f : 0.0f;
                s_w[p][xh - r0] += valid ? lx * 0.25f : 0.0f;
                maxidx = max(maxidx, xh - r0);
            }
            s_cnt[p] = maxidx + 1;
            s_off[p] = (unsigned)(((b << 9) + r0) << 10);
        }
    } else {
        const int p = l >> 2;                // bin
        const int s = l & 3;                 // sample
        const float x = start + ((float)p + ((float)s + 0.5f) * 0.25f) * bin;
        const bool valid = (x >= -1.0f) && (x <= (float)TLEN);
        const float xc = fminf(fmaxf(x, 0.0f), (float)(TLEN - 1));
        const int xl = (int)floorf(xc);
        const int xh = min(xl + 1, TLEN - 1);
        const float lx = xc - (float)xl;
        uint4 d;
        d.x = (unsigned)(((b << 9) + xl) << 10);
        d.y = (unsigned)(((b << 9) + xh) << 10);
        d.z = __float_as_uint(valid ? (1.0f - lx) : 0.0f);
        d.w = __float_as_uint(valid ? lx : 0.0f);
        s_desc[l] = d;
    }
    __syncthreads();

    const char* base = (const char*)g_tr + l * 16;   // this thread's channels

    // ---- Phase B: gather + accumulate + stage ----
    if (contig) {
        #pragma unroll 1
        for (int p = 0; p < PBIN; p += 2) {
            const unsigned offA = s_off[p];
            const unsigned offB = s_off[p + 1];
            const float* wA = s_w[p];
            const float* wB = s_w[p + 1];
            const int cj = max(s_cnt[p], s_cnt[p + 1]);
            float4 aA = make_float4(0.0f, 0.0f, 0.0f, 0.0f);
            float4 aB = make_float4(0.0f, 0.0f, 0.0f, 0.0f);
            #pragma unroll 3
            for (int j = 0; j < cj; j++) {
                const float4 vA = *(const float4*)(base + offA + (unsigned)j * 1024u);
                const float4 vB = *(const float4*)(base + offB + (unsigned)j * 1024u);
                const float ka = wA[j];
                const float kb = wB[j];
                aA.x += vA.x * ka; aA.y += vA.y * ka; aA.z += vA.z * ka; aA.w += vA.w * ka;
                aB.x += vB.x * kb; aB.y += vB.y * kb; aB.z += vB.z * kb; aB.w += vB.w * kb;
            }
            s_stage[p * 64 + ((l + p + (p >> 2)) & 63)] = aA;
            const int q = p + 1;
            s_stage[q * 64 + ((l + q + (q >> 2)) & 63)] = aB;
        }
    } else {
        #pragma unroll 2
        for (int p = 0; p < PBIN; p++) {
            float4 acc = make_float4(0.0f, 0.0f, 0.0f, 0.0f);
            #pragma unroll
            for (int s = 0; s < SRAT; s++) {
                const uint4 d = s_desc[p * SRAT + s];
                const float4 vlo = *(const float4*)(base + d.x);
                const float4 vhi = *(const float4*)(base + d.y);
                const float wlo = __uint_as_float(d.z);
                const float whi = __uint_as_float(d.w);
                acc.x += vlo.x * wlo + vhi.x * whi;
                acc.y += vlo.y * wlo + vhi.y * whi;
                acc.z += vlo.z * wlo + vhi.z * whi;
                acc.w += vlo.w * wlo + vhi.w * whi;
            }
            acc.x *= 0.25f; acc.y *= 0.25f; acc.z *= 0.25f; acc.w *= 0.25f;
            s_stage[p * 64 + ((l + p + (p >> 2)) & 63)] = acc;
        }
    }
    __syncthreads();

    // ---- Phase C: coalesced writeback (identical to R2 champion) ----
    float4* outn = out + (size_t)n * (CH * PBIN / 4);
    const float* st = (const float*)s_stage;

    #pragma unroll
    for (int k = 0; k < 16; k++) {
        const int q = l + 64 * k;        // output float4 index (coalesced)
        const int c = q >> 2;            // channel
        const int g = q & 3;             // p-group
        const int t = c >> 2;            // staged float4 column (pre-rotation)
        const int j = c & 3;             // component within staged float4
        const int p0 = 4 * g;
        float4 v;
        v.x = st[(p0 + 0) * 256 + 4 * ((t + (p0 + 0) + ((p0 + 0) >> 2)) & 63) + j];
        v.y = st[(p0 + 1) * 256 + 4 * ((t + (p0 + 1) + ((p0 + 1) >> 2)) & 63) + j];
        v.z = st[(p0 + 2) * 256 + 4 * ((t + (p0 + 2) + ((p0 + 2) >> 2)) & 63) + j];
        v.w = st[(p0 + 3) * 256 + 4 * ((t + (p0 + 3) + ((p0 + 3) >> 2)) & 63) + j];
        outn[q] = v;
    }
}

extern "C" void kernel_launch(void* const* d_in, const int* in_sizes, int n_in,
                              void* d_out, int out_size) {
    const float* input = (const float*)d_in[0];
    const float* rois  = (const float*)d_in[1];
    float4*      out   = (float4*)d_out;

    const int N = in_sizes[1] / 3;       // 2048 ROIs

    dim3 tgrid(TLEN / 32, CH / 32, BS);  // (16, 8, 8)
    dim3 tblk(32, 8);
    transpose_kernel<<<tgrid, tblk>>>(input);

    roialign_kernel<<<N, 64>>>(rois, out);
}